// round 13
// baseline (speedup 1.0000x reference)
#include <cuda_runtime.h>
#include <cuda_fp16.h>
#include <cstdint>

// Problem constants
#define NBATCH 128
#define D1     1024
#define D2     512
#define DD1    512
#define DD2    256

// GEMM tiling (fp16 kernels: 128 x 256 CTA tile, 8 warps of 64x64)
#define BM 128
#define BN2 256
#define BK 64                  // fp16 elements per k-stage
#define ROWA 144               // A smem row stride (128B data + 16B pad)
#define ROWX2 528              // B-trans row stride (512B data + 16B pad)
#define ROW8 80                // fp8 smem row stride (64B data + 16B pad)
#define A_TILE   (128 * ROWA)  // 18432
#define BT2_TILE (64 * ROWX2)  // 33792 (B trans: 64 k-rows x 512B)
#define BN2_TILE (256 * ROWA)  // 36864 (B non-trans: 256 n-rows)
#define A8_TILE  (128 * ROW8)  // 10240

typedef __half h16;

// ---------------------------------------------------------------------------
// Scratch (allocation-free __device__ globals)
// ---------------------------------------------------------------------------
__device__ h16     g_sh [(size_t)NBATCH * DD1 * D2];
__device__ h16     g_xh [(size_t)NBATCH * D1 * D2];   // x as fp16, same layout
__device__ h16     g_hhi[(size_t)NBATCH * DD1 * D2];
__device__ uint8_t g_h8 [(size_t)NBATCH * DD1 * D2];  // h as e4m3
__device__ h16     g_ghi[(size_t)NBATCH * DD1 * D2];
__device__ h16     g_W1Th[(size_t)DD1 * D1];
__device__ h16     g_W2Th[(size_t)DD2 * D2];
__device__ uint8_t g_Wm8T[(size_t)D2 * D2];           // Wm^T as e4m3

// ---------------------------------------------------------------------------
// Helpers
// ---------------------------------------------------------------------------
__device__ __forceinline__ uint32_t smem_u32(const void* p) {
    uint32_t a;
    asm("{ .reg .u64 t; cvta.to.shared.u64 t, %1; cvt.u32.u64 %0, t; }"
        : "=r"(a) : "l"(p));
    return a;
}
__device__ __forceinline__ void cpa16(uint32_t s, const void* g) {
    asm volatile("cp.async.cg.shared.global [%0], [%1], 16;"
                 :: "r"(s), "l"(__cvta_generic_to_global(g)));
}
#define CP_COMMIT() asm volatile("cp.async.commit_group;" ::: "memory")
#define CP_WAIT1()  asm volatile("cp.async.wait_group 1;"  ::: "memory")

__device__ __forceinline__ void ldmx4(uint32_t* r, uint32_t addr) {
    asm volatile("ldmatrix.sync.aligned.m8n8.x4.shared.b16 {%0,%1,%2,%3}, [%4];"
                 : "=r"(r[0]), "=r"(r[1]), "=r"(r[2]), "=r"(r[3]) : "r"(addr));
}
__device__ __forceinline__ void ldmx4t(uint32_t* r, uint32_t addr) {
    asm volatile("ldmatrix.sync.aligned.m8n8.x4.trans.shared.b16 {%0,%1,%2,%3}, [%4];"
                 : "=r"(r[0]), "=r"(r[1]), "=r"(r[2]), "=r"(r[3]) : "r"(addr));
}
__device__ __forceinline__ void mma_f16(float* d, const uint32_t* a,
                                        uint32_t b0, uint32_t b1) {
    asm volatile(
        "mma.sync.aligned.m16n8k16.row.col.f32.f16.f16.f32 "
        "{%0,%1,%2,%3}, {%4,%5,%6,%7}, {%8,%9}, {%0,%1,%2,%3};"
        : "+f"(d[0]), "+f"(d[1]), "+f"(d[2]), "+f"(d[3])
        : "r"(a[0]), "r"(a[1]), "r"(a[2]), "r"(a[3]), "r"(b0), "r"(b1));
}
__device__ __forceinline__ void mma_e4m3(float* d, const uint32_t* a,
                                         uint32_t b0, uint32_t b1) {
    asm volatile(
        "mma.sync.aligned.m16n8k32.row.col.f32.e4m3.e4m3.f32 "
        "{%0,%1,%2,%3}, {%4,%5,%6,%7}, {%8,%9}, {%0,%1,%2,%3};"
        : "+f"(d[0]), "+f"(d[1]), "+f"(d[2]), "+f"(d[3])
        : "r"(a[0]), "r"(a[1]), "r"(a[2]), "r"(a[3]), "r"(b0), "r"(b1));
}
// Pack two fp32 into e4m3x2 (v0 in low byte). .b16 destination.
__device__ __forceinline__ uint16_t pack_e4m3x2(float v0, float v1) {
    uint16_t r;
    asm("cvt.rn.satfinite.e4m3x2.f32 %0, %1, %2;" : "=h"(r) : "f"(v1), "f"(v0));
    return r;
}

// ---------------------------------------------------------------------------
// fp16 batched GEMM, CTA tile 128x256, warp tile 64x64 (8 warps, 2Mx4N).
// Intra-stage software-pipelined fragments; 2-stage cp.async double buffer
// (issue AFTER compute — kt+2 reuses buf).
//   BTRANS=0: C[z] = A[z] (MxK) @ B[z]^T, B stored [N][K]
//   BTRANS=1: C[z] = A[z] (MxK) @ B[z],   B stored [K][N] (ldb = row stride)
// EPI: 1 = fp16 hi + e4m3 C (G1); 2 = fp32 C + bias (G3)
// ---------------------------------------------------------------------------
template <int EPI, bool BTRANS>
__global__ void __launch_bounds__(256)
mma_gemm_kernel(const h16* __restrict__ A_, const h16* __restrict__ B_,
                float* __restrict__ C, h16* __restrict__ Chi,
                uint8_t* __restrict__ C8, const float* __restrict__ bias,
                int K, int N, int ldb, long sA, long sB, long sC)
{
    constexpr uint32_t BTILE  = BTRANS ? BT2_TILE : BN2_TILE;
    constexpr uint32_t STAGEB = A_TILE + BTILE;

    extern __shared__ char smem[];
    const uint32_t sb = smem_u32(smem);
    const int tid = threadIdx.x, lane = tid & 31, wid = tid >> 5;
    const int z = blockIdx.z;
    const int m0 = blockIdx.y * BM, n0 = blockIdx.x * BN2;

    const h16* Ab = A_ + (size_t)z * sA + (size_t)m0 * K;
    const h16* Bb = BTRANS ? B_ + (size_t)z * sB + n0
                           : B_ + (size_t)z * sB + (size_t)n0 * K;

    const int NK = K / BK;
    const int warp_m = (wid & 1) * 64;
    const int warp_n = (wid >> 1) * 64;
    const uint32_t laddr = (uint32_t)((lane & 15) * ROWA + (lane >> 4) * 16);

    float acc[4][8][4];
#pragma unroll
    for (int i = 0; i < 4; i++)
#pragma unroll
        for (int j = 0; j < 8; j++)
#pragma unroll
            for (int k = 0; k < 4; k++) acc[i][j][k] = 0.0f;

    auto issue = [&](int st, int buf) {
        const int k0 = st * BK;
        const uint32_t base = sb + buf * STAGEB;
        // A: 128 rows x 8 segs of 16B = 1024 ops / 256 thr
#pragma unroll
        for (int j = 0; j < 4; j++) {
            int c = tid + j * 256;
            int row = c >> 3, seg = c & 7;
            cpa16(base + row * ROWA + seg * 16,
                  Ab + (size_t)row * K + k0 + seg * 8);
        }
        // B: 2048 ops / 256 thr
#pragma unroll
        for (int j = 0; j < 8; j++) {
            int c = tid + j * 256;
            if (BTRANS) {      // 64 k-rows x 32 segs of 16B
                int row = c >> 5, seg = c & 31;
                cpa16(base + A_TILE + row * ROWX2 + seg * 16,
                      Bb + (size_t)(k0 + row) * ldb + seg * 8);
            } else {           // 256 n-rows x 8 segs of 16B
                int row = c >> 3, seg = c & 7;
                cpa16(base + A_TILE + row * ROWA + seg * 16,
                      Bb + (size_t)row * K + k0 + seg * 8);
            }
        }
    };

    issue(0, 0); CP_COMMIT();
    issue(1, 1); CP_COMMIT();

    for (int kt = 0; kt < NK; kt++) {
        const int buf = kt & 1;
        CP_WAIT1();
        __syncthreads();

        const uint32_t abase = sb + buf * STAGEB;
        const uint32_t bbase = abase + A_TILE;

        auto ldA = [&](uint32_t (*Af)[4], int kh) {
#pragma unroll
            for (int mt = 0; mt < 4; mt++)
                ldmx4(Af[mt], abase + (warp_m + mt * 16) * ROWA + kh * 32 + laddr);
        };
        auto ldB = [&](uint32_t (*Bf)[4], int kh) {
#pragma unroll
            for (int p = 0; p < 4; p++) {
                if (BTRANS)
                    ldmx4t(Bf[p], bbase + (kh * 16 + (lane & 15)) * ROWX2
                                + warp_n * 2 + p * 32 + (lane >> 4) * 16);
                else
                    ldmx4(Bf[p], bbase + (warp_n + p * 16) * ROWA + kh * 32 + laddr);
            }
        };

        uint32_t Af[2][4][4], Bf[4][4];
        ldB(Bf, 0);
        ldA(Af[0], 0);

#pragma unroll
        for (int kh = 0; kh < 4; kh++) {
            const int cur = kh & 1;
            // HMMA group 1: mt 0,1 (16 HMMA)
#pragma unroll
            for (int mt = 0; mt < 2; mt++)
#pragma unroll
                for (int nt = 0; nt < 8; nt++) {
                    const int p = nt >> 1, o = nt & 1;
                    if (BTRANS)
                        mma_f16(acc[mt][nt], Af[cur][mt], Bf[p][2 * o], Bf[p][2 * o + 1]);
                    else
                        mma_f16(acc[mt][nt], Af[cur][mt], Bf[p][o], Bf[p][o + 2]);
                }
            // prefetch next kh's A fragments (overlaps with HMMA group 2)
            if (kh < 3) ldA(Af[cur ^ 1], kh + 1);
            // HMMA group 2: mt 2,3 (16 HMMA)
#pragma unroll
            for (int mt = 2; mt < 4; mt++)
#pragma unroll
                for (int nt = 0; nt < 8; nt++) {
                    const int p = nt >> 1, o = nt & 1;
                    if (BTRANS)
                        mma_f16(acc[mt][nt], Af[cur][mt], Bf[p][2 * o], Bf[p][2 * o + 1]);
                    else
                        mma_f16(acc[mt][nt], Af[cur][mt], Bf[p][o], Bf[p][o + 2]);
                }
            // reload B in place (all consumers issued; WAR within thread is safe)
            if (kh < 3) ldB(Bf, kh + 1);
        }

        // All warps done reading buf before cp.async overwrites it (kt+2 -> same buf)
        __syncthreads();
        if (kt + 2 < NK) issue(kt + 2, buf);
        CP_COMMIT();
    }

    // ---- epilogue ----
#pragma unroll
    for (int mt = 0; mt < 4; mt++)
#pragma unroll
        for (int nt = 0; nt < 8; nt++) {
            int r = m0 + warp_m + mt * 16 + (lane >> 2);
            int cc = n0 + warp_n + nt * 8 + 2 * (lane & 3);
            float v0 = acc[mt][nt][0], v1 = acc[mt][nt][1];
            float v2 = acc[mt][nt][2], v3 = acc[mt][nt][3];
            if (EPI == 2) {
                float2 b0 = *(const float2*)(bias + (size_t)r * N + cc);
                float2 b1 = *(const float2*)(bias + (size_t)(r + 8) * N + cc);
                v0 += b0.x; v1 += b0.y; v2 += b1.x; v3 += b1.y;
                float* Cb = C + (size_t)z * sC;
                *(float2*)(Cb + (size_t)r * N + cc)       = make_float2(v0, v1);
                *(float2*)(Cb + (size_t)(r + 8) * N + cc) = make_float2(v2, v3);
            }
            if (EPI == 1) {
                __half2 p0 = __floats2half2_rn(v0, v1);
                __half2 p1 = __floats2half2_rn(v2, v3);
                h16* chb = Chi + (size_t)z * sC;
                uint8_t* c8b = C8 + (size_t)z * sC;
                *(uint32_t*)(chb + (size_t)r * N + cc)       = *(uint32_t*)&p0;
                *(uint32_t*)(chb + (size_t)(r + 8) * N + cc) = *(uint32_t*)&p1;
                *(uint16_t*)(c8b + (size_t)r * N + cc)       = pack_e4m3x2(v0, v1);
                *(uint16_t*)(c8b + (size_t)(r + 8) * N + cc) = pack_e4m3x2(v2, v3);
            }
        }
}

// ---------------------------------------------------------------------------
// fp8 batched GEMM (G2): C[z] = A[z] (MxK, e4m3) @ B^T (B: [N][K] e4m3)
// 128x128 tile, 8 warps 64x32. Output fp16.
// ---------------------------------------------------------------------------
__global__ void __launch_bounds__(256, 2)
mma_gemm_fp8_kernel(const uint8_t* __restrict__ A_, const uint8_t* __restrict__ B_,
                    h16* __restrict__ Ch, int K, int N, long sA, long sC)
{
    constexpr uint32_t STAGEB = 2 * A8_TILE;

    extern __shared__ char smem[];
    const uint32_t sb = smem_u32(smem);
    const int tid = threadIdx.x, lane = tid & 31, wid = tid >> 5;
    const int z = blockIdx.z;
    const int m0 = blockIdx.y * BM, n0 = blockIdx.x * 128;

    const uint8_t* Ab = A_ + (size_t)z * sA + (size_t)m0 * K;
    const uint8_t* Bb = B_ + (size_t)n0 * K;

    const int NK = K / BK;
    const int warp_m = (wid & 1) * 64;
    const int warp_n = (wid >> 1) * 32;
    const uint32_t laddr = (uint32_t)((lane & 15) * ROW8 + (lane >> 4) * 16);

    float acc[4][4][4];
#pragma unroll
    for (int i = 0; i < 4; i++)
#pragma unroll
        for (int j = 0; j < 4; j++)
#pragma unroll
            for (int k = 0; k < 4; k++) acc[i][j][k] = 0.0f;

    auto issue = [&](int st, int buf) {
        const int k0 = st * BK;
        const uint32_t base = sb + buf * STAGEB;
#pragma unroll
        for (int j = 0; j < 2; j++) {
            int c = tid + j * 256;
            int row = c >> 2, seg = c & 3;
            cpa16(base + row * ROW8 + seg * 16,
                  Ab + (size_t)row * K + k0 + seg * 16);
            cpa16(base + A8_TILE + row * ROW8 + seg * 16,
                  Bb + (size_t)row * K + k0 + seg * 16);
        }
    };

    issue(0, 0); CP_COMMIT();
    issue(1, 1); CP_COMMIT();

    for (int kt = 0; kt < NK; kt++) {
        const int buf = kt & 1;
        CP_WAIT1();
        __syncthreads();

        const uint32_t abase = sb + buf * STAGEB;
        const uint32_t bbase = abase + A8_TILE;

        auto ldA = [&](uint32_t (*Af)[4], int kh) {
#pragma unroll
            for (int mt = 0; mt < 4; mt++)
                ldmx4(Af[mt], abase + (warp_m + mt * 16) * ROW8 + kh * 32 + laddr);
        };
        auto ldB = [&](uint32_t (*Bf)[4], int kh) {
#pragma unroll
            for (int p = 0; p < 2; p++)
                ldmx4(Bf[p], bbase + (warp_n + p * 16) * ROW8 + kh * 32 + laddr);
        };

        uint32_t Af[2][4][4], Bf[2][4];
        ldB(Bf, 0);
        ldA(Af[0], 0);

#pragma unroll
        for (int kh = 0; kh < 2; kh++) {
            const int cur = kh & 1;
#pragma unroll
            for (int mt = 0; mt < 2; mt++)
#pragma unroll
                for (int nt = 0; nt < 4; nt++) {
                    const int p = nt >> 1, o = nt & 1;
                    mma_e4m3(acc[mt][nt], Af[cur][mt], Bf[p][o], Bf[p][o + 2]);
                }
            if (kh < 1) ldA(Af[cur ^ 1], kh + 1);
#pragma unroll
            for (int mt = 2; mt < 4; mt++)
#pragma unroll
                for (int nt = 0; nt < 4; nt++) {
                    const int p = nt >> 1, o = nt & 1;
                    mma_e4m3(acc[mt][nt], Af[cur][mt], Bf[p][o], Bf[p][o + 2]);
                }
            if (kh < 1) ldB(Bf, kh + 1);
        }

        __syncthreads();
        if (kt + 2 < NK) issue(kt + 2, buf);
        CP_COMMIT();
    }

#pragma unroll
    for (int mt = 0; mt < 4; mt++)
#pragma unroll
        for (int nt = 0; nt < 4; nt++) {
            int r = m0 + warp_m + mt * 16 + (lane >> 2);
            int cc = n0 + warp_n + nt * 8 + 2 * (lane & 3);
            __half2 p0 = __floats2half2_rn(acc[mt][nt][0], acc[mt][nt][1]);
            __half2 p1 = __floats2half2_rn(acc[mt][nt][2], acc[mt][nt][3]);
            h16* cb = Ch + (size_t)z * sC;
            *(uint32_t*)(cb + (size_t)r * N + cc)       = *(uint32_t*)&p0;
            *(uint32_t*)(cb + (size_t)(r + 8) * N + cc) = *(uint32_t*)&p1;
        }
}

// ---------------------------------------------------------------------------
// Convert fp32 -> fp16 (same layout), vectorized
// ---------------------------------------------------------------------------
__global__ void convert_h_kernel(const float* __restrict__ in,
                                 h16* __restrict__ out, size_t n4)
{
    size_t i = (size_t)blockIdx.x * blockDim.x + threadIdx.x;
    if (i < n4) {
        float4 v = *(const float4*)(in + i * 4);
        __half2 p0 = __floats2half2_rn(v.x, v.y);
        __half2 p1 = __floats2half2_rn(v.z, v.w);
        *(uint2*)(out + i * 4) = make_uint2(*(uint32_t*)&p0, *(uint32_t*)&p1);
    }
}

// Transpose: in fp32 [R][C] -> out fp16 [C][R]  (weights only)
__global__ void transpose_h_kernel(const float* __restrict__ in,
                                   h16* __restrict__ oh, int R, int Ccols)
{
    __shared__ float t[32][33];
    int c0 = blockIdx.x * 32, r0 = blockIdx.y * 32;
#pragma unroll
    for (int i = threadIdx.y; i < 32; i += 8)
        t[i][threadIdx.x] = in[(size_t)(r0 + i) * Ccols + c0 + threadIdx.x];
    __syncthreads();
#pragma unroll
    for (int i = threadIdx.y; i < 32; i += 8)
        oh[(size_t)(c0 + i) * R + r0 + threadIdx.x] =
            __float2half_rn(t[threadIdx.x][i]);
}

// Wm8T[v][w] = e4m3( (w==v) ? 1/D2 : W[w][v] )
__global__ void build_wm8T_kernel(const float* __restrict__ W) {
    int idx = blockIdx.x * blockDim.x + threadIdx.x;
    int v = idx / D2, w = idx % D2;
    float val = (w == v) ? (1.0f / (float)D2) : W[(size_t)w * D2 + v];
    uint16_t r;
    asm("cvt.rn.satfinite.e4m3x2.f32 %0, %1, %2;" : "=h"(r) : "f"(0.0f), "f"(val));
    g_Wm8T[idx] = (uint8_t)(r & 0xFF);
}

// ---------------------------------------------------------------------------
// softmax over last axis (512) + gate: g = a*h + (1-a)*h*softmax(s)
// ---------------------------------------------------------------------------
__global__ void __launch_bounds__(128)
softmax_gate_kernel(const float* __restrict__ alpha_p)
{
    const size_t base = (size_t)blockIdx.x * D2;
    const int t = threadIdx.x;

    __half2 s0 = *(const __half2*)(g_sh + base + t * 4);
    __half2 s1 = *(const __half2*)(g_sh + base + t * 4 + 2);
    float sv0 = __low2float(s0), sv1 = __high2float(s0);
    float sv2 = __low2float(s1), sv3 = __high2float(s1);

    float m = fmaxf(fmaxf(sv0, sv1), fmaxf(sv2, sv3));
    __shared__ float red[4];
#pragma unroll
    for (int o = 16; o > 0; o >>= 1)
        m = fmaxf(m, __shfl_xor_sync(0xFFFFFFFFu, m, o));
    if ((t & 31) == 0) red[t >> 5] = m;
    __syncthreads();
    m = fmaxf(fmaxf(red[0], red[1]), fmaxf(red[2], red[3]));

    float e0 = __expf(sv0 - m), e1 = __expf(sv1 - m);
    float e2 = __expf(sv2 - m), e3 = __expf(sv3 - m);
    float sum = e0 + e1 + e2 + e3;
#pragma unroll
    for (int o = 16; o > 0; o >>= 1)
        sum += __shfl_xor_sync(0xFFFFFFFFu, sum, o);
    __syncthreads();
    if ((t & 31) == 0) red[t >> 5] = sum;
    __syncthreads();
    sum = red[0] + red[1] + red[2] + red[3];
    float inv = 1.0f / sum;

    float a = fminf(fmaxf(alpha_p[0], 0.0f), 10.0f);
    float oma = 1.0f - a;

    __half2 hh0 = *(const __half2*)(g_hhi + base + t * 4);
    __half2 hh1 = *(const __half2*)(g_hhi + base + t * 4 + 2);
    float hv0 = __low2float(hh0), hv1 = __high2float(hh0);
    float hv2 = __low2float(hh1), hv3 = __high2float(hh1);

    float g0 = a * hv0 + oma * hv0 * (e0 * inv);
    float g1 = a * hv1 + oma * hv1 * (e1 * inv);
    float g2 = a * hv2 + oma * hv2 * (e2 * inv);
    float g3 = a * hv3 + oma * hv3 * (e3 * inv);

    __half2 p0 = __floats2half2_rn(g0, g1);
    __half2 p1 = __floats2half2_rn(g2, g3);
    *(uint2*)(g_ghi + base + t * 4) =
        make_uint2(*(uint32_t*)&p0, *(uint32_t*)&p1);
}

// ---------------------------------------------------------------------------
// Launch
// ---------------------------------------------------------------------------
extern "C" void kernel_launch(void* const* d_in, const int* in_sizes, int n_in,
                              void* d_out, int out_size)
{
    const float* x     = (const float*)d_in[0];
    const float* W1    = (const float*)d_in[1];
    const float* W2    = (const float*)d_in[2];
    const float* W     = (const float*)d_in[3];
    const float* alpha = (const float*)d_in[4];
    const float* bias  = (const float*)d_in[5];
    float* out = (float*)d_out;

    h16 *sh, *xh, *hhi, *ghi, *W1Th, *W2Th;
    uint8_t *h8, *wm8;
    cudaGetSymbolAddress((void**)&sh,   g_sh);
    cudaGetSymbolAddress((void**)&xh,   g_xh);
    cudaGetSymbolAddress((void**)&hhi,  g_hhi);
    cudaGetSymbolAddress((void**)&h8,   g_h8);
    cudaGetSymbolAddress((void**)&ghi,  g_ghi);
    cudaGetSymbolAddress((void**)&W1Th, g_W1Th);
    cudaGetSymbolAddress((void**)&W2Th, g_W2Th);
    cudaGetSymbolAddress((void**)&wm8,  g_Wm8T);

    const int SM_G1 = 2 * (A_TILE + BT2_TILE);  // 104448
    const int SM_G3 = 2 * (A_TILE + BN2_TILE);  // 110592
    const int SM_G2 = 2 * 2 * A8_TILE;          // 40960
    cudaFuncSetAttribute((const void*)mma_gemm_kernel<1, true>,
                         cudaFuncAttributeMaxDynamicSharedMemorySize, SM_G1);
    cudaFuncSetAttribute((const void*)mma_gemm_kernel<2, false>,
                         cudaFuncAttributeMaxDynamicSharedMemorySize, SM_G3);
    cudaFuncSetAttribute((const void*)mma_gemm_fp8_kernel,
                         cudaFuncAttributeMaxDynamicSharedMemorySize, SM_G2);

    // Prep (keeps G1 at launch index 5 for ncu capture)
    size_t n4 = (size_t)NBATCH * D1 * D2 / 4;
    convert_h_kernel<<<(unsigned)((n4 + 255) / 256), 256>>>(x, xh, n4);
    build_wm8T_kernel<<<(D2 * D2) / 256, 256>>>(W);
    transpose_h_kernel<<<dim3(DD1 / 32, D1 / 32, 1), dim3(32, 8)>>>(
        W1, W1Th, D1, DD1);

    // G1: h[z] = W1Th (512x1024) @ xh[z] ([K=1024][N=512], trans-B)
    mma_gemm_kernel<1, true><<<dim3(D2 / BN2, DD1 / BM, NBATCH), 256, SM_G1>>>(
        W1Th, xh, nullptr, hhi, h8, nullptr,
        D1, D2, /*ldb=*/D2, 0L, (long)D1 * D2, (long)DD1 * D2);

    // G2 (fp8): s[z] = h8[z] @ Wm8T^T -> fp16 s
    mma_gemm_fp8_kernel<<<dim3(D2 / 128, DD1 / BM, NBATCH), 256, SM_G2>>>(
        h8, wm8, sh, D2, D2, (long)DD1 * D2, (long)DD1 * D2);

    // softmax + gate -> g (fp16)
    softmax_gate_kernel<<<NBATCH * DD1, 128>>>(alpha);

    // W2 transpose (only needed by G3)
    transpose_h_kernel<<<dim3(DD2 / 32, D2 / 32, 1), dim3(32, 8)>>>(
        W2, W2Th, D2, DD2);

    // G3: out[z] = ghi[z] @ W2Th^T + bias -> fp32 out
    mma_gemm_kernel<2, false><<<dim3(DD2 / BN2, DD1 / BM, NBATCH), 256, SM_G3>>>(
        ghi, W2Th, out, nullptr, nullptr, bias,
        D2, DD2, /*ldb=*/0, (long)DD1 * D2, 0L, (long)DD1 * DD2);
}

// round 14
// speedup vs baseline: 1.1005x; 1.1005x over previous
#include <cuda_runtime.h>
#include <cuda_fp16.h>
#include <cstdint>

// Problem constants
#define NBATCH 128
#define D1     1024
#define D2     512
#define DD1    512
#define DD2    256

// GEMM tiling (fp16 kernels: 128x128 CTA tile, 8 warps of 64x32 — R12 config)
#define BM 128
#define BN 128
#define BK 64                  // fp16 elements per k-stage
#define ROWA 144               // A smem row stride (128B data + 16B pad)
#define ROWX 272               // B-trans smem row stride (256B data + 16B pad)
#define ROW8 80                // fp8 smem row stride (64B data + 16B pad)
#define A_TILE  (128 * ROWA)   // 18432
#define BT_TILE (64 * ROWX)    // 17408
#define BN_TILE (128 * ROWA)   // 18432
#define A8_TILE (128 * ROW8)   // 10240

typedef __half h16;

// ---------------------------------------------------------------------------
// Scratch (allocation-free __device__ globals)
// ---------------------------------------------------------------------------
__device__ h16     g_sh [(size_t)NBATCH * DD1 * D2];
__device__ h16     g_xh [(size_t)NBATCH * D1 * D2];
__device__ h16     g_hhi[(size_t)NBATCH * DD1 * D2];
__device__ uint8_t g_h8 [(size_t)NBATCH * DD1 * D2];
__device__ h16     g_ghi[(size_t)NBATCH * DD1 * D2];
__device__ h16     g_W1Th[(size_t)DD1 * D1];
__device__ h16     g_W2Th[(size_t)DD2 * D2];
__device__ uint8_t g_Wm8T[(size_t)D2 * D2];

// ---------------------------------------------------------------------------
// Helpers
// ---------------------------------------------------------------------------
__device__ __forceinline__ uint32_t smem_u32(const void* p) {
    uint32_t a;
    asm("{ .reg .u64 t; cvta.to.shared.u64 t, %1; cvt.u32.u64 %0, t; }"
        : "=r"(a) : "l"(p));
    return a;
}
__device__ __forceinline__ void cpa16(uint32_t s, const void* g) {
    asm volatile("cp.async.cg.shared.global [%0], [%1], 16;"
                 :: "r"(s), "l"(__cvta_generic_to_global(g)));
}
#define CP_COMMIT() asm volatile("cp.async.commit_group;" ::: "memory")
#define CP_WAIT1()  asm volatile("cp.async.wait_group 1;"  ::: "memory")

__device__ __forceinline__ void ldmx4(uint32_t* r, uint32_t addr) {
    asm volatile("ldmatrix.sync.aligned.m8n8.x4.shared.b16 {%0,%1,%2,%3}, [%4];"
                 : "=r"(r[0]), "=r"(r[1]), "=r"(r[2]), "=r"(r[3]) : "r"(addr));
}
__device__ __forceinline__ void ldmx4t(uint32_t* r, uint32_t addr) {
    asm volatile("ldmatrix.sync.aligned.m8n8.x4.trans.shared.b16 {%0,%1,%2,%3}, [%4];"
                 : "=r"(r[0]), "=r"(r[1]), "=r"(r[2]), "=r"(r[3]) : "r"(addr));
}
__device__ __forceinline__ void mma_f16(float* d, const uint32_t* a,
                                        uint32_t b0, uint32_t b1) {
    asm volatile(
        "mma.sync.aligned.m16n8k16.row.col.f32.f16.f16.f32 "
        "{%0,%1,%2,%3}, {%4,%5,%6,%7}, {%8,%9}, {%0,%1,%2,%3};"
        : "+f"(d[0]), "+f"(d[1]), "+f"(d[2]), "+f"(d[3])
        : "r"(a[0]), "r"(a[1]), "r"(a[2]), "r"(a[3]), "r"(b0), "r"(b1));
}
// fp8 MMA with fp16 accumulators (rate-theory test)
__device__ __forceinline__ void mma_e4m3_h(uint32_t* d, const uint32_t* a,
                                           uint32_t b0, uint32_t b1) {
    asm volatile(
        "mma.sync.aligned.m16n8k32.row.col.f16.e4m3.e4m3.f16 "
        "{%0,%1}, {%2,%3,%4,%5}, {%6,%7}, {%0,%1};"
        : "+r"(d[0]), "+r"(d[1])
        : "r"(a[0]), "r"(a[1]), "r"(a[2]), "r"(a[3]), "r"(b0), "r"(b1));
}
// Pack two fp32 into e4m3x2 (v0 in low byte). .b16 destination.
__device__ __forceinline__ uint16_t pack_e4m3x2(float v0, float v1) {
    uint16_t r;
    asm("cvt.rn.satfinite.e4m3x2.f32 %0, %1, %2;" : "=h"(r) : "f"(v1), "f"(v0));
    return r;
}

// ---------------------------------------------------------------------------
// fp16 batched GEMM (R12 config): CTA 128x128, 8 warps 64x32, intra-stage
// pipelined fragments, 2-stage cp.async (issue AFTER compute).
//   BTRANS=0: C[z] = A[z] (MxK) @ B[z]^T, B stored [N][K]
//   BTRANS=1: C[z] = A[z] (MxK) @ B[z],   B stored [K][N] (ldb = row stride)
// EPI: 1 = fp16 hi + e4m3 C (G1); 2 = fp32 C + bias (G3)
// ---------------------------------------------------------------------------
template <int EPI, bool BTRANS>
__global__ void __launch_bounds__(256, 2)
mma_gemm_kernel(const h16* __restrict__ A_, const h16* __restrict__ B_,
                float* __restrict__ C, h16* __restrict__ Chi,
                uint8_t* __restrict__ C8, const float* __restrict__ bias,
                int K, int N, int ldb, long sA, long sB, long sC)
{
    constexpr uint32_t BTILE  = BTRANS ? BT_TILE : BN_TILE;
    constexpr uint32_t STAGEB = A_TILE + BTILE;

    extern __shared__ char smem[];
    const uint32_t sb = smem_u32(smem);
    const int tid = threadIdx.x, lane = tid & 31, wid = tid >> 5;
    const int z = blockIdx.z;
    const int m0 = blockIdx.y * BM, n0 = blockIdx.x * BN;

    const h16* Ab = A_ + (size_t)z * sA + (size_t)m0 * K;
    const h16* Bb = BTRANS ? B_ + (size_t)z * sB + n0
                           : B_ + (size_t)z * sB + (size_t)n0 * K;

    const int NK = K / BK;
    const int warp_m = (wid & 1) * 64;
    const int warp_n = (wid >> 1) * 32;
    const uint32_t laddr = (uint32_t)((lane & 15) * ROWA + (lane >> 4) * 16);

    float acc[4][4][4];
#pragma unroll
    for (int i = 0; i < 4; i++)
#pragma unroll
        for (int j = 0; j < 4; j++)
#pragma unroll
            for (int k = 0; k < 4; k++) acc[i][j][k] = 0.0f;

    auto issue = [&](int st, int buf) {
        const int k0 = st * BK;
        const uint32_t base = sb + buf * STAGEB;
#pragma unroll
        for (int j = 0; j < 4; j++) {
            int c = tid + j * 256;
            int row = c >> 3, seg = c & 7;
            cpa16(base + row * ROWA + seg * 16,
                  Ab + (size_t)row * K + k0 + seg * 8);
        }
#pragma unroll
        for (int j = 0; j < 4; j++) {
            int c = tid + j * 256;
            if (BTRANS) {
                int row = c >> 4, seg = c & 15;
                cpa16(base + A_TILE + row * ROWX + seg * 16,
                      Bb + (size_t)(k0 + row) * ldb + seg * 8);
            } else {
                int row = c >> 3, seg = c & 7;
                cpa16(base + A_TILE + row * ROWA + seg * 16,
                      Bb + (size_t)row * K + k0 + seg * 8);
            }
        }
    };

    issue(0, 0); CP_COMMIT();
    issue(1, 1); CP_COMMIT();

    for (int kt = 0; kt < NK; kt++) {
        const int buf = kt & 1;
        CP_WAIT1();
        __syncthreads();

        const uint32_t abase = sb + buf * STAGEB;
        const uint32_t bbase = abase + A_TILE;

        auto ldA = [&](uint32_t (*Af)[4], int kh) {
#pragma unroll
            for (int mt = 0; mt < 4; mt++)
                ldmx4(Af[mt], abase + (warp_m + mt * 16) * ROWA + kh * 32 + laddr);
        };
        auto ldB = [&](uint32_t (*Bf)[4], int kh) {
#pragma unroll
            for (int p = 0; p < 2; p++) {
                if (BTRANS)
                    ldmx4t(Bf[p], bbase + (kh * 16 + (lane & 15)) * ROWX
                                + warp_n * 2 + p * 32 + (lane >> 4) * 16);
                else
                    ldmx4(Bf[p], bbase + (warp_n + p * 16) * ROWA + kh * 32 + laddr);
            }
        };

        uint32_t Af[2][4][4], Bf[2][4];
        ldB(Bf, 0);
        ldA(Af[0], 0);

#pragma unroll
        for (int kh = 0; kh < 4; kh++) {
            const int cur = kh & 1;
#pragma unroll
            for (int mt = 0; mt < 2; mt++)
#pragma unroll
                for (int nt = 0; nt < 4; nt++) {
                    const int p = nt >> 1, o = nt & 1;
                    if (BTRANS)
                        mma_f16(acc[mt][nt], Af[cur][mt], Bf[p][2 * o], Bf[p][2 * o + 1]);
                    else
                        mma_f16(acc[mt][nt], Af[cur][mt], Bf[p][o], Bf[p][o + 2]);
                }
            if (kh < 3) ldA(Af[cur ^ 1], kh + 1);
#pragma unroll
            for (int mt = 2; mt < 4; mt++)
#pragma unroll
                for (int nt = 0; nt < 4; nt++) {
                    const int p = nt >> 1, o = nt & 1;
                    if (BTRANS)
                        mma_f16(acc[mt][nt], Af[cur][mt], Bf[p][2 * o], Bf[p][2 * o + 1]);
                    else
                        mma_f16(acc[mt][nt], Af[cur][mt], Bf[p][o], Bf[p][o + 2]);
                }
            if (kh < 3) ldB(Bf, kh + 1);
        }

        __syncthreads();
        if (kt + 2 < NK) issue(kt + 2, buf);
        CP_COMMIT();
    }

    // ---- epilogue ----
#pragma unroll
    for (int mt = 0; mt < 4; mt++)
#pragma unroll
        for (int nt = 0; nt < 4; nt++) {
            int r = m0 + warp_m + mt * 16 + (lane >> 2);
            int cc = n0 + warp_n + nt * 8 + 2 * (lane & 3);
            float v0 = acc[mt][nt][0], v1 = acc[mt][nt][1];
            float v2 = acc[mt][nt][2], v3 = acc[mt][nt][3];
            if (EPI == 2) {
                float2 b0 = *(const float2*)(bias + (size_t)r * N + cc);
                float2 b1 = *(const float2*)(bias + (size_t)(r + 8) * N + cc);
                v0 += b0.x; v1 += b0.y; v2 += b1.x; v3 += b1.y;
                float* Cb = C + (size_t)z * sC;
                *(float2*)(Cb + (size_t)r * N + cc)       = make_float2(v0, v1);
                *(float2*)(Cb + (size_t)(r + 8) * N + cc) = make_float2(v2, v3);
            }
            if (EPI == 1) {
                __half2 p0 = __floats2half2_rn(v0, v1);
                __half2 p1 = __floats2half2_rn(v2, v3);
                h16* chb = Chi + (size_t)z * sC;
                uint8_t* c8b = C8 + (size_t)z * sC;
                *(uint32_t*)(chb + (size_t)r * N + cc)       = *(uint32_t*)&p0;
                *(uint32_t*)(chb + (size_t)(r + 8) * N + cc) = *(uint32_t*)&p1;
                *(uint16_t*)(c8b + (size_t)r * N + cc)       = pack_e4m3x2(v0, v1);
                *(uint16_t*)(c8b + (size_t)(r + 8) * N + cc) = pack_e4m3x2(v2, v3);
            }
        }
}

// ---------------------------------------------------------------------------
// fp8 batched GEMM (G2), fp16 ACCUMULATORS: C[z] = A[z] @ B^T, out fp16.
// ---------------------------------------------------------------------------
__global__ void __launch_bounds__(256, 2)
mma_gemm_fp8_kernel(const uint8_t* __restrict__ A_, const uint8_t* __restrict__ B_,
                    h16* __restrict__ Ch, int K, int N, long sA, long sC)
{
    constexpr uint32_t STAGEB = 2 * A8_TILE;

    extern __shared__ char smem[];
    const uint32_t sb = smem_u32(smem);
    const int tid = threadIdx.x, lane = tid & 31, wid = tid >> 5;
    const int z = blockIdx.z;
    const int m0 = blockIdx.y * BM, n0 = blockIdx.x * 128;

    const uint8_t* Ab = A_ + (size_t)z * sA + (size_t)m0 * K;
    const uint8_t* Bb = B_ + (size_t)n0 * K;

    const int NK = K / BK;
    const int warp_m = (wid & 1) * 64;
    const int warp_n = (wid >> 1) * 32;
    const uint32_t laddr = (uint32_t)((lane & 15) * ROW8 + (lane >> 4) * 16);

    uint32_t hacc[4][4][2];
#pragma unroll
    for (int i = 0; i < 4; i++)
#pragma unroll
        for (int j = 0; j < 4; j++) { hacc[i][j][0] = 0; hacc[i][j][1] = 0; }

    auto issue = [&](int st, int buf) {
        const int k0 = st * BK;
        const uint32_t base = sb + buf * STAGEB;
#pragma unroll
        for (int j = 0; j < 2; j++) {
            int c = tid + j * 256;
            int row = c >> 2, seg = c & 3;
            cpa16(base + row * ROW8 + seg * 16,
                  Ab + (size_t)row * K + k0 + seg * 16);
            cpa16(base + A8_TILE + row * ROW8 + seg * 16,
                  Bb + (size_t)row * K + k0 + seg * 16);
        }
    };

    issue(0, 0); CP_COMMIT();
    issue(1, 1); CP_COMMIT();

    for (int kt = 0; kt < NK; kt++) {
        const int buf = kt & 1;
        CP_WAIT1();
        __syncthreads();

        const uint32_t abase = sb + buf * STAGEB;
        const uint32_t bbase = abase + A8_TILE;

        auto ldA = [&](uint32_t (*Af)[4], int kh) {
#pragma unroll
            for (int mt = 0; mt < 4; mt++)
                ldmx4(Af[mt], abase + (warp_m + mt * 16) * ROW8 + kh * 32 + laddr);
        };
        auto ldB = [&](uint32_t (*Bf)[4], int kh) {
#pragma unroll
            for (int p = 0; p < 2; p++)
                ldmx4(Bf[p], bbase + (warp_n + p * 16) * ROW8 + kh * 32 + laddr);
        };

        uint32_t Af[2][4][4], Bf[2][4];
        ldB(Bf, 0);
        ldA(Af[0], 0);

#pragma unroll
        for (int kh = 0; kh < 2; kh++) {
            const int cur = kh & 1;
#pragma unroll
            for (int mt = 0; mt < 2; mt++)
#pragma unroll
                for (int nt = 0; nt < 4; nt++) {
                    const int p = nt >> 1, o = nt & 1;
                    mma_e4m3_h(hacc[mt][nt], Af[cur][mt], Bf[p][o], Bf[p][o + 2]);
                }
            if (kh < 1) ldA(Af[cur ^ 1], kh + 1);
#pragma unroll
            for (int mt = 2; mt < 4; mt++)
#pragma unroll
                for (int nt = 0; nt < 4; nt++) {
                    const int p = nt >> 1, o = nt & 1;
                    mma_e4m3_h(hacc[mt][nt], Af[cur][mt], Bf[p][o], Bf[p][o + 2]);
                }
            if (kh < 1) ldB(Bf, kh + 1);
        }

        __syncthreads();
        if (kt + 2 < NK) issue(kt + 2, buf);
        CP_COMMIT();
    }

    // epilogue: hacc[..][0] = packed (r, cc..cc+1); hacc[..][1] = (r+8, ..)
#pragma unroll
    for (int mt = 0; mt < 4; mt++)
#pragma unroll
        for (int nt = 0; nt < 4; nt++) {
            int r = m0 + warp_m + mt * 16 + (lane >> 2);
            int cc = n0 + warp_n + nt * 8 + 2 * (lane & 3);
            h16* cb = Ch + (size_t)z * sC;
            *(uint32_t*)(cb + (size_t)r * N + cc)       = hacc[mt][nt][0];
            *(uint32_t*)(cb + (size_t)(r + 8) * N + cc) = hacc[mt][nt][1];
        }
}

// ---------------------------------------------------------------------------
// Convert fp32 -> fp16 (same layout), vectorized
// ---------------------------------------------------------------------------
__global__ void convert_h_kernel(const float* __restrict__ in,
                                 h16* __restrict__ out, size_t n4)
{
    size_t i = (size_t)blockIdx.x * blockDim.x + threadIdx.x;
    if (i < n4) {
        float4 v = *(const float4*)(in + i * 4);
        __half2 p0 = __floats2half2_rn(v.x, v.y);
        __half2 p1 = __floats2half2_rn(v.z, v.w);
        *(uint2*)(out + i * 4) = make_uint2(*(uint32_t*)&p0, *(uint32_t*)&p1);
    }
}

// Transpose: in fp32 [R][C] -> out fp16 [C][R]  (weights only)
__global__ void transpose_h_kernel(const float* __restrict__ in,
                                   h16* __restrict__ oh, int R, int Ccols)
{
    __shared__ float t[32][33];
    int c0 = blockIdx.x * 32, r0 = blockIdx.y * 32;
#pragma unroll
    for (int i = threadIdx.y; i < 32; i += 8)
        t[i][threadIdx.x] = in[(size_t)(r0 + i) * Ccols + c0 + threadIdx.x];
    __syncthreads();
#pragma unroll
    for (int i = threadIdx.y; i < 32; i += 8)
        oh[(size_t)(c0 + i) * R + r0 + threadIdx.x] =
            __float2half_rn(t[threadIdx.x][i]);
}

// Wm8T[v][w] = e4m3( (w==v) ? 1/D2 : W[w][v] )
__global__ void build_wm8T_kernel(const float* __restrict__ W) {
    int idx = blockIdx.x * blockDim.x + threadIdx.x;
    int v = idx / D2, w = idx % D2;
    float val = (w == v) ? (1.0f / (float)D2) : W[(size_t)w * D2 + v];
    uint16_t r;
    asm("cvt.rn.satfinite.e4m3x2.f32 %0, %1, %2;" : "=h"(r) : "f"(0.0f), "f"(val));
    g_Wm8T[idx] = (uint8_t)(r & 0xFF);
}

// ---------------------------------------------------------------------------
// softmax over last axis (512) + gate: g = a*h + (1-a)*h*softmax(s)
// ---------------------------------------------------------------------------
__global__ void __launch_bounds__(128)
softmax_gate_kernel(const float* __restrict__ alpha_p)
{
    const size_t base = (size_t)blockIdx.x * D2;
    const int t = threadIdx.x;

    __half2 s0 = *(const __half2*)(g_sh + base + t * 4);
    __half2 s1 = *(const __half2*)(g_sh + base + t * 4 + 2);
    float sv0 = __low2float(s0), sv1 = __high2float(s0);
    float sv2 = __low2float(s1), sv3 = __high2float(s1);

    float m = fmaxf(fmaxf(sv0, sv1), fmaxf(sv2, sv3));
    __shared__ float red[4];
#pragma unroll
    for (int o = 16; o > 0; o >>= 1)
        m = fmaxf(m, __shfl_xor_sync(0xFFFFFFFFu, m, o));
    if ((t & 31) == 0) red[t >> 5] = m;
    __syncthreads();
    m = fmaxf(fmaxf(red[0], red[1]), fmaxf(red[2], red[3]));

    float e0 = __expf(sv0 - m), e1 = __expf(sv1 - m);
    float e2 = __expf(sv2 - m), e3 = __expf(sv3 - m);
    float sum = e0 + e1 + e2 + e3;
#pragma unroll
    for (int o = 16; o > 0; o >>= 1)
        sum += __shfl_xor_sync(0xFFFFFFFFu, sum, o);
    __syncthreads();
    if ((t & 31) == 0) red[t >> 5] = sum;
    __syncthreads();
    sum = red[0] + red[1] + red[2] + red[3];
    float inv = 1.0f / sum;

    float a = fminf(fmaxf(alpha_p[0], 0.0f), 10.0f);
    float oma = 1.0f - a;

    __half2 hh0 = *(const __half2*)(g_hhi + base + t * 4);
    __half2 hh1 = *(const __half2*)(g_hhi + base + t * 4 + 2);
    float hv0 = __low2float(hh0), hv1 = __high2float(hh0);
    float hv2 = __low2float(hh1), hv3 = __high2float(hh1);

    float g0 = a * hv0 + oma * hv0 * (e0 * inv);
    float g1 = a * hv1 + oma * hv1 * (e1 * inv);
    float g2 = a * hv2 + oma * hv2 * (e2 * inv);
    float g3 = a * hv3 + oma * hv3 * (e3 * inv);

    __half2 p0 = __floats2half2_rn(g0, g1);
    __half2 p1 = __floats2half2_rn(g2, g3);
    *(uint2*)(g_ghi + base + t * 4) =
        make_uint2(*(uint32_t*)&p0, *(uint32_t*)&p1);
}

// ---------------------------------------------------------------------------
// Launch
// ---------------------------------------------------------------------------
extern "C" void kernel_launch(void* const* d_in, const int* in_sizes, int n_in,
                              void* d_out, int out_size)
{
    const float* x     = (const float*)d_in[0];
    const float* W1    = (const float*)d_in[1];
    const float* W2    = (const float*)d_in[2];
    const float* W     = (const float*)d_in[3];
    const float* alpha = (const float*)d_in[4];
    const float* bias  = (const float*)d_in[5];
    float* out = (float*)d_out;

    h16 *sh, *xh, *hhi, *ghi, *W1Th, *W2Th;
    uint8_t *h8, *wm8;
    cudaGetSymbolAddress((void**)&sh,   g_sh);
    cudaGetSymbolAddress((void**)&xh,   g_xh);
    cudaGetSymbolAddress((void**)&hhi,  g_hhi);
    cudaGetSymbolAddress((void**)&h8,   g_h8);
    cudaGetSymbolAddress((void**)&ghi,  g_ghi);
    cudaGetSymbolAddress((void**)&W1Th, g_W1Th);
    cudaGetSymbolAddress((void**)&W2Th, g_W2Th);
    cudaGetSymbolAddress((void**)&wm8,  g_Wm8T);

    const int SM_G1 = 2 * (A_TILE + BT_TILE);   // 71680
    const int SM_G3 = 2 * (A_TILE + BN_TILE);   // 73728
    const int SM_G2 = 2 * 2 * A8_TILE;          // 40960
    cudaFuncSetAttribute((const void*)mma_gemm_kernel<1, true>,
                         cudaFuncAttributeMaxDynamicSharedMemorySize, SM_G1);
    cudaFuncSetAttribute((const void*)mma_gemm_kernel<2, false>,
                         cudaFuncAttributeMaxDynamicSharedMemorySize, SM_G3);
    cudaFuncSetAttribute((const void*)mma_gemm_fp8_kernel,
                         cudaFuncAttributeMaxDynamicSharedMemorySize, SM_G2);

    // Prep (keeps G1 at launch index 5 for ncu capture)
    size_t n4 = (size_t)NBATCH * D1 * D2 / 4;
    convert_h_kernel<<<(unsigned)((n4 + 255) / 256), 256>>>(x, xh, n4);
    build_wm8T_kernel<<<(D2 * D2) / 256, 256>>>(W);
    transpose_h_kernel<<<dim3(DD1 / 32, D1 / 32, 1), dim3(32, 8)>>>(
        W1, W1Th, D1, DD1);

    // G1: h[z] = W1Th (512x1024) @ xh[z] ([K=1024][N=512], trans-B)
    mma_gemm_kernel<1, true><<<dim3(D2 / BN, DD1 / BM, NBATCH), 256, SM_G1>>>(
        W1Th, xh, nullptr, hhi, h8, nullptr,
        D1, D2, /*ldb=*/D2, 0L, (long)D1 * D2, (long)DD1 * D2);

    // G2 (fp8, fp16 acc): s[z] = h8[z] @ Wm8T^T -> fp16 s
    mma_gemm_fp8_kernel<<<dim3(D2 / 128, DD1 / BM, NBATCH), 256, SM_G2>>>(
        h8, wm8, sh, D2, D2, (long)DD1 * D2, (long)DD1 * D2);

    // softmax + gate -> g (fp16)
    softmax_gate_kernel<<<NBATCH * DD1, 128>>>(alpha);

    // W2 transpose (only needed by G3)
    transpose_h_kernel<<<dim3(DD2 / 32, D2 / 32, 1), dim3(32, 8)>>>(
        W2, W2Th, D2, DD2);

    // G3: out[z] = ghi[z] @ W2Th^T + bias -> fp32 out
    mma_gemm_kernel<2, false><<<dim3(DD2 / BN, DD1 / BM, NBATCH), 256, SM_G3>>>(
        ghi, W2Th, out, nullptr, nullptr, bias,
        D2, DD2, /*ldb=*/0, (long)DD1 * D2, 0L, (long)DD1 * DD2);
}